// round 1
// baseline (speedup 1.0000x reference)
#include <cuda_runtime.h>
#include <cuda_bf16.h>
#include <cstddef>

// Problem constants
#define BB 8
#define SEQ 4096
#define CC 1024
#define HH 16
#define DD 64
#define MM (BB*SEQ)          // 32768
#define C3 (3*CC)            // 3072
#define BH (BB*HH)           // 128
#define EPS 1e-6f

// ---------------- scratch (device globals; no allocation allowed) ----------------
__device__ float g_qkv[(size_t)MM * C3];   // [M][3C]  q | k | v   (q,k overwritten in-place by focus)
__device__ float g_kv[(size_t)BH * DD * DD];
__device__ float g_ksum[BH * DD];
__device__ float g_o[(size_t)MM * CC];

// =================================================================================
// SGEMM (TN): C[m,n] = sum_k A[m,k] * W[n,k]  (+ optional bias[n])
// 128x128 block tile, BK=8, 256 threads, 8x8 micro-tile, packed f32x2 FMA.
// =================================================================================
__global__ __launch_bounds__(256) void sgemm_tn(
    const float* __restrict__ A, const float* __restrict__ W,
    const float* __restrict__ bias, float* __restrict__ C,
    int M, int Nn, int K)
{
    __shared__ float As[8][128];
    __shared__ float Ws[8][128];
    const int t = threadIdx.x;
    const int m0 = blockIdx.y * 128;
    const int n0 = blockIdx.x * 128;
    const int lrow = t >> 1;
    const int lk = (t & 1) << 2;
    const float* Ap = A + (size_t)(m0 + lrow) * K + lk;
    const float* Wp = W + (size_t)(n0 + lrow) * K + lk;
    const int tm = (t >> 4) << 3;
    const int tn = (t & 15) << 3;

    unsigned long long acc2[8][4];
#pragma unroll
    for (int i = 0; i < 8; i++)
#pragma unroll
        for (int j = 0; j < 4; j++) acc2[i][j] = 0ULL;

    for (int k0 = 0; k0 < K; k0 += 8) {
        float4 av = *(const float4*)(Ap + k0);
        float4 wv = *(const float4*)(Wp + k0);
        As[lk + 0][lrow] = av.x; As[lk + 1][lrow] = av.y;
        As[lk + 2][lrow] = av.z; As[lk + 3][lrow] = av.w;
        Ws[lk + 0][lrow] = wv.x; Ws[lk + 1][lrow] = wv.y;
        Ws[lk + 2][lrow] = wv.z; Ws[lk + 3][lrow] = wv.w;
        __syncthreads();
#pragma unroll
        for (int kk = 0; kk < 8; kk++) {
            float a[8];
            *(float4*)(a)     = *(const float4*)(&As[kk][tm]);
            *(float4*)(a + 4) = *(const float4*)(&As[kk][tm + 4]);
            unsigned long long b2[4];
            *(ulonglong2*)(b2)     = *(const ulonglong2*)(&Ws[kk][tn]);
            *(ulonglong2*)(b2 + 2) = *(const ulonglong2*)(&Ws[kk][tn + 4]);
#pragma unroll
            for (int i = 0; i < 8; i++) {
                unsigned long long a2;
                asm("mov.b64 %0, {%1, %1};" : "=l"(a2) : "f"(a[i]));
#pragma unroll
                for (int j = 0; j < 4; j++)
                    asm("fma.rn.f32x2 %0, %1, %2, %0;" : "+l"(acc2[i][j]) : "l"(a2), "l"(b2[j]));
            }
        }
        __syncthreads();
    }

#pragma unroll
    for (int i = 0; i < 8; i++) {
        float out[8];
#pragma unroll
        for (int j = 0; j < 4; j++)
            asm("mov.b64 {%0, %1}, %2;" : "=f"(out[2 * j]), "=f"(out[2 * j + 1]) : "l"(acc2[i][j]));
        if (bias) {
#pragma unroll
            for (int j = 0; j < 8; j++) out[j] += bias[n0 + tn + j];
        }
        float* crow = C + (size_t)(m0 + tm + i) * Nn + n0 + tn;
        *(float4*)(crow)     = *(float4*)(out);
        *(float4*)(crow + 4) = *(float4*)(out + 4);
    }
}

// =================================================================================
// Focus kernel: per row (b,n) of q,k: relu+eps, /softplus(scale), k+=pos_enc,
// then t -> t^3 / ||t^3|| * ||t||  (norms over full C=1024). In-place on g_qkv.
// =================================================================================
__global__ __launch_bounds__(256) void focus_kernel(
    const float* __restrict__ scale, const float* __restrict__ pos_enc)
{
    const int row = blockIdx.x;                 // b*SEQ + n
    const int n = row & (SEQ - 1);
    float* qp = g_qkv + (size_t)row * C3;
    float* kp = qp + CC;
    const int t = threadIdx.x;
    const int c0 = t * 4;

    float4 q4 = *(float4*)(qp + c0);
    float4 k4 = *(float4*)(kp + c0);
    const float4 pe  = *(const float4*)(pos_enc + (size_t)n * CC + c0);
    const float4 sc4 = *(const float4*)(scale + c0);

    float qv[4] = {q4.x, q4.y, q4.z, q4.w};
    float kv[4] = {k4.x + pe.x, k4.y + pe.y, k4.z + pe.z, k4.w + pe.w};
    float sv[4] = {sc4.x, sc4.y, sc4.z, sc4.w};

    float s2q = 0.f, s6q = 0.f, s2k = 0.f, s6k = 0.f;
#pragma unroll
    for (int j = 0; j < 4; j++) {
        float sc = log1pf(expf(sv[j]));         // softplus
        float q = (fmaxf(qv[j], 0.f) + EPS) / sc;
        float k = (fmaxf(kv[j], 0.f) + EPS) / sc;
        qv[j] = q; kv[j] = k;
        float q2 = q * q, k2 = k * k;
        s2q += q2; s2k += k2;
        float q3 = q2 * q, k3 = k2 * k;
        s6q += q3 * q3; s6k += k3 * k3;
    }

    // block reduce 4 sums
    __shared__ float red[8][4];
    const int lid = t & 31, wid = t >> 5;
#pragma unroll
    for (int o = 16; o > 0; o >>= 1) {
        s2q += __shfl_xor_sync(0xffffffffu, s2q, o);
        s6q += __shfl_xor_sync(0xffffffffu, s6q, o);
        s2k += __shfl_xor_sync(0xffffffffu, s2k, o);
        s6k += __shfl_xor_sync(0xffffffffu, s6k, o);
    }
    if (lid == 0) { red[wid][0] = s2q; red[wid][1] = s6q; red[wid][2] = s2k; red[wid][3] = s6k; }
    __syncthreads();
    float t2q = 0.f, t6q = 0.f, t2k = 0.f, t6k = 0.f;
#pragma unroll
    for (int w = 0; w < 8; w++) {
        t2q += red[w][0]; t6q += red[w][1]; t2k += red[w][2]; t6k += red[w][3];
    }
    const float fq = sqrtf(t2q / t6q);
    const float fk = sqrtf(t2k / t6k);

    float4 qo, ko;
    float* qvo = (float*)&qo; float* kvo = (float*)&ko;
#pragma unroll
    for (int j = 0; j < 4; j++) {
        qvo[j] = qv[j] * qv[j] * qv[j] * fq;
        kvo[j] = kv[j] * kv[j] * kv[j] * fk;
    }
    *(float4*)(qp + c0) = qo;
    *(float4*)(kp + c0) = ko;
}

// =================================================================================
// zero kv/ksum accumulators
// =================================================================================
__global__ void zero_kv_kernel()
{
    int i = blockIdx.x * 256 + threadIdx.x;
    if (i < BH * DD * DD) g_kv[i] = 0.f;
    if (i < BH * DD)      g_ksum[i] = 0.f;
}

// =================================================================================
// kv kernel: per (b,h, n-split): kv[c][d] += sum_n k[n][c]*v[n][d]; ksum[c] += ...
// 64 threads, 8x8 micro-tile over the 64x64 output; atomic accumulate.
// =================================================================================
#define NSPLIT 8
#define NCHUNK (SEQ / NSPLIT)   // 512
__global__ __launch_bounds__(64) void kv_kernel()
{
    const int bh = blockIdx.x;                  // 0..127
    const int sp = blockIdx.y;                  // 0..NSPLIT-1
    const int b = bh >> 4, h = bh & 15;
    const int n0 = sp * NCHUNK;
    __shared__ float ks[32][64];
    __shared__ float vs[32][64];
    const int t = threadIdx.x;                  // 64
    const int tc = (t >> 3) << 3;
    const int td = (t & 7) << 3;
    float acc[8][8] = {};
    float ksacc = 0.f;                          // ksum for channel t

    for (int nt = 0; nt < NCHUNK; nt += 32) {
#pragma unroll
        for (int l = 0; l < 8; l++) {
            int idx4 = t + l * 64;              // 0..511
            int nn = idx4 >> 4, q4 = (idx4 & 15) << 2;
            size_t base = ((size_t)(b * SEQ + n0 + nt + nn)) * C3 + h * DD + q4;
            *(float4*)&ks[nn][q4] = *(const float4*)&g_qkv[base + CC];
            *(float4*)&vs[nn][q4] = *(const float4*)&g_qkv[base + 2 * CC];
        }
        __syncthreads();
#pragma unroll 4
        for (int nn = 0; nn < 32; nn++) {
            float a[8], bb[8];
            *(float4*)(a)      = *(float4*)&ks[nn][tc];
            *(float4*)(a + 4)  = *(float4*)&ks[nn][tc + 4];
            *(float4*)(bb)     = *(float4*)&vs[nn][td];
            *(float4*)(bb + 4) = *(float4*)&vs[nn][td + 4];
#pragma unroll
            for (int i = 0; i < 8; i++)
#pragma unroll
                for (int j = 0; j < 8; j++) acc[i][j] += a[i] * bb[j];
            ksacc += ks[nn][t];
        }
        __syncthreads();
    }
#pragma unroll
    for (int i = 0; i < 8; i++)
#pragma unroll
        for (int j = 0; j < 8; j++)
            atomicAdd(&g_kv[((size_t)bh * DD + tc + i) * DD + td + j], acc[i][j]);
    atomicAdd(&g_ksum[bh * DD + t], ksacc);
}

// =================================================================================
// o kernel: per (b,h, 64-row chunk): z_i = 1/(q_i . ksum + eps); o_i = z_i * q_i @ kv
// writes merged-head layout g_o[b, i, h*64 + d]
// =================================================================================
__global__ __launch_bounds__(256) void o_kernel()
{
    const int bh = blockIdx.x;                  // 128
    const int ic = blockIdx.y;                  // 64 chunks of 64 rows
    const int b = bh >> 4, h = bh & 15;
    const int i0 = ic * 64;
    __shared__ float qs[64][68];                // [c][r], padded stride (16B aligned)
    __shared__ float kvs[64][64];
    __shared__ float ks_s[64];
    __shared__ float z_s[64];
    const int t = threadIdx.x;

    for (int idx = t; idx < DD * DD; idx += 256)
        kvs[idx >> 6][idx & 63] = g_kv[(size_t)bh * DD * DD + idx];
    if (t < 64) ks_s[t] = g_ksum[bh * DD + t];
    for (int idx = t; idx < 64 * 64; idx += 256) {
        int r = idx >> 6, c = idx & 63;
        qs[c][r] = g_qkv[((size_t)(b * SEQ + i0 + r)) * C3 + h * DD + c];
    }
    __syncthreads();

    if (t < 64) {
        float s = 0.f;
#pragma unroll 8
        for (int c = 0; c < 64; c++) s += qs[c][t] * ks_s[c];
        z_s[t] = 1.0f / (s + EPS);
    }
    __syncthreads();

    const int tm = (t >> 5) << 3;               // 8 row-strips
    const int tn = (t & 31) << 1;               // 2 cols
    float acc[8][2] = {};
#pragma unroll 8
    for (int c = 0; c < 64; c++) {
        float a[8];
        *(float4*)(a)     = *(float4*)&qs[c][tm];
        *(float4*)(a + 4) = *(float4*)&qs[c][tm + 4];
        float2 bv = *(float2*)&kvs[c][tn];
#pragma unroll
        for (int i = 0; i < 8; i++) {
            acc[i][0] += a[i] * bv.x;
            acc[i][1] += a[i] * bv.y;
        }
    }
#pragma unroll
    for (int i = 0; i < 8; i++) {
        float z = z_s[tm + i];
        size_t off = ((size_t)(b * SEQ + i0 + tm + i)) * CC + h * DD + tn;
        g_o[off]     = acc[i][0] * z;
        g_o[off + 1] = acc[i][1] * z;
    }
}

// =================================================================================
extern "C" void kernel_launch(void* const* d_in, const int* in_sizes, int n_in,
                              void* d_out, int out_size)
{
    const float* x       = (const float*)d_in[0];
    const float* scale   = (const float*)d_in[1];
    const float* pos_enc = (const float*)d_in[2];
    const float* qkv_w   = (const float*)d_in[3];
    const float* proj_w  = (const float*)d_in[4];
    const float* proj_b  = (const float*)d_in[5];
    float* out = (float*)d_out;

    float *qkv_p = nullptr, *o_p = nullptr;
    cudaGetSymbolAddress((void**)&qkv_p, g_qkv);
    cudaGetSymbolAddress((void**)&o_p, g_o);

    // 1) qkv = x @ qkv_w^T
    sgemm_tn<<<dim3(C3 / 128, MM / 128), 256>>>(x, qkv_w, nullptr, qkv_p, MM, C3, CC);
    // 2) focusing / activation (in-place on q,k)
    focus_kernel<<<MM, 256>>>(scale, pos_enc);
    // 3) kv = k^T v (+ ksum), accumulated atomically
    zero_kv_kernel<<<(BH * DD * DD + 255) / 256, 256>>>();
    kv_kernel<<<dim3(BH, NSPLIT), 64>>>();
    // 4) o = z * (q @ kv), merged-head layout
    o_kernel<<<dim3(BH, SEQ / 64), 256>>>();
    // 5) out = o @ proj_w^T + proj_b
    sgemm_tn<<<dim3(CC / 128, MM / 128), 256>>>(o_p, proj_w, proj_b, out, MM, CC, CC);
}

// round 3
// speedup vs baseline: 2.2631x; 2.2631x over previous
#include <cuda_runtime.h>
#include <cuda_bf16.h>
#include <cstdint>
#include <cstddef>

// Problem constants
#define BB 8
#define SEQ 4096
#define CC 1024
#define HH 16
#define DD 64
#define MM (BB*SEQ)          // 32768
#define C3 (3*CC)            // 3072
#define BH (BB*HH)           // 128
#define EPS 1e-6f
#define K2 2048              // split operand width (hi | lo)

// ---------------- scratch (device globals; no allocation allowed) ----------------
__device__ float g_qkv[(size_t)MM * C3];          // q | k | v  (f32, focus in-place)
__device__ float g_kv[(size_t)BH * DD * DD];
__device__ float g_ksum[BH * DD];
__device__ __nv_bfloat16 g_x2[(size_t)MM * K2];   // x split   [M][hi(1024)|lo(1024)]
__device__ __nv_bfloat16 g_o2[(size_t)MM * K2];   // o split
__device__ __nv_bfloat16 g_wq2[(size_t)C3 * K2];  // qkv_w split
__device__ __nv_bfloat16 g_wp2[(size_t)CC * K2];  // proj_w split

// ================================ helpers ========================================
__device__ __forceinline__ uint32_t smem_u32(const void* p) {
    uint32_t a;
    asm("{ .reg .u64 t; cvta.to.shared.u64 t, %1; cvt.u32.u64 %0, t; }" : "=r"(a) : "l"(p));
    return a;
}
__device__ __forceinline__ void cpa16(uint32_t sa, const void* g) {
    size_t ga = __cvta_generic_to_global(g);
    asm volatile("cp.async.cg.shared.global [%0], [%1], 16;" :: "r"(sa), "l"(ga) : "memory");
}
__device__ __forceinline__ void ldsm4(uint32_t* d, uint32_t addr) {
    asm volatile("ldmatrix.sync.aligned.m8n8.x4.shared.b16 {%0,%1,%2,%3}, [%4];"
        : "=r"(d[0]), "=r"(d[1]), "=r"(d[2]), "=r"(d[3]) : "r"(addr));
}
__device__ __forceinline__ void mma_bf16(float* c, const uint32_t* a, const uint32_t* b) {
    asm volatile("mma.sync.aligned.m16n8k16.row.col.f32.bf16.bf16.f32 "
        "{%0,%1,%2,%3}, {%4,%5,%6,%7}, {%8,%9}, {%0,%1,%2,%3};"
        : "+f"(c[0]), "+f"(c[1]), "+f"(c[2]), "+f"(c[3])
        : "r"(a[0]), "r"(a[1]), "r"(a[2]), "r"(a[3]), "r"(b[0]), "r"(b[1]));
}

// ============================ HMMA split GEMM ====================================
// C[m,n] = sum_k A[m,k]*B[n,k] (fp32 via bf16 split: Ah*Bh + Al*Bh + Ah*Bl)
// A2: [M][2048] bf16 (hi|lo), B2: [Nn][2048] bf16 (hi|lo).
// BM=128, BN=128, BK=32; 256 threads; warp tile 64x32 (2x4 warp grid).
#define GBM 128
#define GBN 128
#define GBK 32
#define NCH (CC / GBK)          // 32 k-chunks
#define SROW 40                 // smem row stride in bf16 (80 bytes)
#define MATB (128 * SROW * 2)   // 10240 B per matrix tile
#define STG (4 * MATB)          // Ah|Al|Bh|Bl = 40960 B per stage
#define GSMEM (2 * STG)         // 81920 B

__device__ __forceinline__ void g2s_chunk(uint32_t sbase,
    const __nv_bfloat16* __restrict__ A2, const __nv_bfloat16* __restrict__ B2,
    int m0, int n0, int k0, int t)
{
#pragma unroll
    for (int i = 0; i < 2; i++) {
        int idx = t + i * 256;            // 512 16B-chunks per matrix
        int r = idx >> 2, ch = idx & 3;
        uint32_t so = r * (SROW * 2) + ch * 16;
        const __nv_bfloat16* ga = A2 + (size_t)(m0 + r) * K2 + k0 + ch * 8;
        cpa16(sbase + 0 * MATB + so, ga);
        cpa16(sbase + 1 * MATB + so, ga + CC);
        const __nv_bfloat16* gb = B2 + (size_t)(n0 + r) * K2 + k0 + ch * 8;
        cpa16(sbase + 2 * MATB + so, gb);
        cpa16(sbase + 3 * MATB + so, gb + CC);
    }
}

__global__ __launch_bounds__(256) void gemm_mma(
    const __nv_bfloat16* __restrict__ A2, const __nv_bfloat16* __restrict__ B2,
    const float* __restrict__ bias, float* __restrict__ C, int Nn)
{
    extern __shared__ char sm[];
    const uint32_t sb = smem_u32(sm);
    const int t = threadIdx.x, lane = t & 31, w = t >> 5;
    const int wm = (w >> 2) * 64, wn = (w & 3) * 32;
    const int m0 = blockIdx.y * GBM, n0 = blockIdx.x * GBN;

    const int lrow = lane & 15;           // ldmatrix source row within 16
    const int lcol = (lane >> 4) << 3;    // ldmatrix k-col select (0 or 8)

    float acc[4][4][4];                   // [mi][nj][c0..c3]
#pragma unroll
    for (int i = 0; i < 4; i++)
#pragma unroll
        for (int j = 0; j < 4; j++)
#pragma unroll
            for (int r = 0; r < 4; r++) acc[i][j][r] = 0.f;

    g2s_chunk(sb, A2, B2, m0, n0, 0, t);
    asm volatile("cp.async.commit_group;" ::: "memory");
    g2s_chunk(sb + STG, A2, B2, m0, n0, GBK, t);
    asm volatile("cp.async.commit_group;" ::: "memory");

    for (int c = 0; c < NCH; c++) {
        const uint32_t st = sb + (c & 1) * STG;
        if (c == NCH - 1) asm volatile("cp.async.wait_group 0;" ::: "memory");
        else              asm volatile("cp.async.wait_group 1;" ::: "memory");
        __syncthreads();

#pragma unroll
        for (int ks = 0; ks < 2; ks++) {
            const int kb = ks * 16;
            uint32_t ah[4][4], al[4][4];
#pragma unroll
            for (int mi = 0; mi < 4; mi++) {
                uint32_t ao = st + (wm + mi * 16 + lrow) * (SROW * 2) + (kb + lcol) * 2;
                ldsm4(ah[mi], ao);
                ldsm4(al[mi], ao + MATB);
            }
            uint32_t bh[4][2], bl[4][2];
#pragma unroll
            for (int bj = 0; bj < 2; bj++) {
                uint32_t r4[4], s4[4];
                uint32_t bo = st + 2 * MATB + (wn + bj * 16 + lrow) * (SROW * 2) + (kb + lcol) * 2;
                ldsm4(r4, bo);
                ldsm4(s4, bo + MATB);
                bh[2 * bj + 0][0] = r4[0]; bh[2 * bj + 0][1] = r4[2];
                bh[2 * bj + 1][0] = r4[1]; bh[2 * bj + 1][1] = r4[3];
                bl[2 * bj + 0][0] = s4[0]; bl[2 * bj + 0][1] = s4[2];
                bl[2 * bj + 1][0] = s4[1]; bl[2 * bj + 1][1] = s4[3];
            }
#pragma unroll
            for (int mi = 0; mi < 4; mi++)
#pragma unroll
                for (int nj = 0; nj < 4; nj++) {
                    mma_bf16(acc[mi][nj], ah[mi], bh[nj]);
                    mma_bf16(acc[mi][nj], al[mi], bh[nj]);
                    mma_bf16(acc[mi][nj], ah[mi], bl[nj]);
                }
        }
        __syncthreads();
        if (c + 2 < NCH) {
            g2s_chunk(st, A2, B2, m0, n0, (c + 2) * GBK, t);
            asm volatile("cp.async.commit_group;" ::: "memory");
        }
    }

    // epilogue
    const int group = lane >> 2, tig = lane & 3;
#pragma unroll
    for (int mi = 0; mi < 4; mi++)
#pragma unroll
        for (int nj = 0; nj < 4; nj++) {
            int r0 = m0 + wm + mi * 16 + group;
            int cc0 = n0 + wn + nj * 8 + tig * 2;
            float b0 = 0.f, b1 = 0.f;
            if (bias) { b0 = bias[cc0]; b1 = bias[cc0 + 1]; }
            float2 v0 = make_float2(acc[mi][nj][0] + b0, acc[mi][nj][1] + b1);
            float2 v1 = make_float2(acc[mi][nj][2] + b0, acc[mi][nj][3] + b1);
            *(float2*)(C + (size_t)r0 * Nn + cc0)       = v0;
            *(float2*)(C + (size_t)(r0 + 8) * Nn + cc0) = v1;
        }
}

// ============================ split f32 -> (hi|lo) bf16 ==========================
__global__ __launch_bounds__(256) void split_kernel(
    const float* __restrict__ in, __nv_bfloat16* __restrict__ out, int rows)
{
    size_t idx = (size_t)blockIdx.x * 256 + threadIdx.x;
    size_t row = idx >> 8;
    if (row >= (size_t)rows) return;
    int c4 = (int)(idx & 255) << 2;
    float4 v = *(const float4*)(in + row * CC + c4);
    float vv[4] = {v.x, v.y, v.z, v.w};
    __nv_bfloat16 hb[4], lb[4];
#pragma unroll
    for (int j = 0; j < 4; j++) {
        hb[j] = __float2bfloat16(vv[j]);
        lb[j] = __float2bfloat16(vv[j] - __bfloat162float(hb[j]));
    }
    *(uint64_t*)(out + row * K2 + c4)      = *(uint64_t*)hb;
    *(uint64_t*)(out + row * K2 + CC + c4) = *(uint64_t*)lb;
}

// ================================== focus ========================================
__global__ __launch_bounds__(256) void focus_kernel(
    const float* __restrict__ scale, const float* __restrict__ pos_enc)
{
    const int row = blockIdx.x;
    const int n = row & (SEQ - 1);
    float* qp = g_qkv + (size_t)row * C3;
    float* kp = qp + CC;
    const int t = threadIdx.x;
    const int c0 = t * 4;

    float4 q4 = *(float4*)(qp + c0);
    float4 k4 = *(float4*)(kp + c0);
    const float4 pe  = *(const float4*)(pos_enc + (size_t)n * CC + c0);
    const float4 sc4 = *(const float4*)(scale + c0);

    float qv[4] = {q4.x, q4.y, q4.z, q4.w};
    float kv[4] = {k4.x + pe.x, k4.y + pe.y, k4.z + pe.z, k4.w + pe.w};
    float sv[4] = {sc4.x, sc4.y, sc4.z, sc4.w};

    float s2q = 0.f, s6q = 0.f, s2k = 0.f, s6k = 0.f;
#pragma unroll
    for (int j = 0; j < 4; j++) {
        float sc = log1pf(expf(sv[j]));
        float q = (fmaxf(qv[j], 0.f) + EPS) / sc;
        float k = (fmaxf(kv[j], 0.f) + EPS) / sc;
        qv[j] = q; kv[j] = k;
        float q2 = q * q, k2 = k * k;
        s2q += q2; s2k += k2;
        float q3 = q2 * q, k3 = k2 * k;
        s6q += q3 * q3; s6k += k3 * k3;
    }
    __shared__ float red[8][4];
    const int lid = t & 31, wid = t >> 5;
#pragma unroll
    for (int o = 16; o > 0; o >>= 1) {
        s2q += __shfl_xor_sync(0xffffffffu, s2q, o);
        s6q += __shfl_xor_sync(0xffffffffu, s6q, o);
        s2k += __shfl_xor_sync(0xffffffffu, s2k, o);
        s6k += __shfl_xor_sync(0xffffffffu, s6k, o);
    }
    if (lid == 0) { red[wid][0] = s2q; red[wid][1] = s6q; red[wid][2] = s2k; red[wid][3] = s6k; }
    __syncthreads();
    float t2q = 0.f, t6q = 0.f, t2k = 0.f, t6k = 0.f;
#pragma unroll
    for (int wq = 0; wq < 8; wq++) {
        t2q += red[wq][0]; t6q += red[wq][1]; t2k += red[wq][2]; t6k += red[wq][3];
    }
    const float fq = sqrtf(t2q / t6q);
    const float fk = sqrtf(t2k / t6k);

    float4 qo, ko;
    float* qvo = (float*)&qo; float* kvo = (float*)&ko;
#pragma unroll
    for (int j = 0; j < 4; j++) {
        qvo[j] = qv[j] * qv[j] * qv[j] * fq;
        kvo[j] = kv[j] * kv[j] * kv[j] * fk;
    }
    *(float4*)(qp + c0) = qo;
    *(float4*)(kp + c0) = ko;
}

__global__ void zero_kv_kernel()
{
    int i = blockIdx.x * 256 + threadIdx.x;
    if (i < BH * DD * DD) g_kv[i] = 0.f;
    if (i < BH * DD)      g_ksum[i] = 0.f;
}

// ==================================== kv =========================================
#define NSPLIT 8
#define NCHUNK (SEQ / NSPLIT)
__global__ __launch_bounds__(64) void kv_kernel()
{
    const int bh = blockIdx.x;
    const int sp = blockIdx.y;
    const int b = bh >> 4, h = bh & 15;
    const int n0 = sp * NCHUNK;
    __shared__ float ks[32][64];
    __shared__ float vs[32][64];
    const int t = threadIdx.x;
    const int tc = (t >> 3) << 3;
    const int td = (t & 7) << 3;
    float acc[8][8] = {};
    float ksacc = 0.f;

    for (int nt = 0; nt < NCHUNK; nt += 32) {
#pragma unroll
        for (int l = 0; l < 8; l++) {
            int idx4 = t + l * 64;
            int nn = idx4 >> 4, q4 = (idx4 & 15) << 2;
            size_t base = ((size_t)(b * SEQ + n0 + nt + nn)) * C3 + h * DD + q4;
            *(float4*)&ks[nn][q4] = *(const float4*)&g_qkv[base + CC];
            *(float4*)&vs[nn][q4] = *(const float4*)&g_qkv[base + 2 * CC];
        }
        __syncthreads();
#pragma unroll 4
        for (int nn = 0; nn < 32; nn++) {
            float a[8], bb[8];
            *(float4*)(a)      = *(float4*)&ks[nn][tc];
            *(float4*)(a + 4)  = *(float4*)&ks[nn][tc + 4];
            *(float4*)(bb)     = *(float4*)&vs[nn][td];
            *(float4*)(bb + 4) = *(float4*)&vs[nn][td + 4];
#pragma unroll
            for (int i = 0; i < 8; i++)
#pragma unroll
                for (int j = 0; j < 8; j++) acc[i][j] += a[i] * bb[j];
            ksacc += ks[nn][t];
        }
        __syncthreads();
    }
#pragma unroll
    for (int i = 0; i < 8; i++)
#pragma unroll
        for (int j = 0; j < 8; j++)
            atomicAdd(&g_kv[((size_t)bh * DD + tc + i) * DD + td + j], acc[i][j]);
    atomicAdd(&g_ksum[bh * DD + t], ksacc);
}

// ============ o kernel: writes split bf16 (hi|lo) directly into g_o2 =============
__global__ __launch_bounds__(256) void o_kernel()
{
    const int bh = blockIdx.x;
    const int ic = blockIdx.y;
    const int b = bh >> 4, h = bh & 15;
    const int i0 = ic * 64;
    __shared__ float qs[64][68];
    __shared__ float kvs[64][64];
    __shared__ float ks_s[64];
    __shared__ float z_s[64];
    const int t = threadIdx.x;

    for (int idx = t; idx < DD * DD; idx += 256)
        kvs[idx >> 6][idx & 63] = g_kv[(size_t)bh * DD * DD + idx];
    if (t < 64) ks_s[t] = g_ksum[bh * DD + t];
    for (int idx = t; idx < 64 * 64; idx += 256) {
        int r = idx >> 6, c = idx & 63;
        qs[c][r] = g_qkv[((size_t)(b * SEQ + i0 + r)) * C3 + h * DD + c];
    }
    __syncthreads();

    if (t < 64) {
        float s = 0.f;
#pragma unroll 8
        for (int c = 0; c < 64; c++) s += qs[c][t] * ks_s[c];
        z_s[t] = 1.0f / (s + EPS);
    }
    __syncthreads();

    const int tm = (t >> 5) << 3;
    const int tn = (t & 31) << 1;
    float acc[8][2] = {};
#pragma unroll 8
    for (int c = 0; c < 64; c++) {
        float a[8];
        *(float4*)(a)     = *(float4*)&qs[c][tm];
        *(float4*)(a + 4) = *(float4*)&qs[c][tm + 4];
        float2 bv = *(float2*)&kvs[c][tn];
#pragma unroll
        for (int i = 0; i < 8; i++) {
            acc[i][0] += a[i] * bv.x;
            acc[i][1] += a[i] * bv.y;
        }
    }
#pragma unroll
    for (int i = 0; i < 8; i++) {
        float z = z_s[tm + i];
        float v0 = acc[i][0] * z, v1 = acc[i][1] * z;
        __nv_bfloat16 hb0 = __float2bfloat16(v0), hb1 = __float2bfloat16(v1);
        __nv_bfloat16 lb0 = __float2bfloat16(v0 - __bfloat162float(hb0));
        __nv_bfloat16 lb1 = __float2bfloat16(v1 - __bfloat162float(hb1));
        size_t off = ((size_t)(b * SEQ + i0 + tm + i)) * K2 + h * DD + tn;
        __nv_bfloat162 hp; hp.x = hb0; hp.y = hb1;
        __nv_bfloat162 lp; lp.x = lb0; lp.y = lb1;
        *(__nv_bfloat162*)(g_o2 + off)      = hp;
        *(__nv_bfloat162*)(g_o2 + off + CC) = lp;
    }
}

// =================================================================================
extern "C" void kernel_launch(void* const* d_in, const int* in_sizes, int n_in,
                              void* d_out, int out_size)
{
    const float* x       = (const float*)d_in[0];
    const float* scale   = (const float*)d_in[1];
    const float* pos_enc = (const float*)d_in[2];
    const float* qkv_w   = (const float*)d_in[3];
    const float* proj_w  = (const float*)d_in[4];
    const float* proj_b  = (const float*)d_in[5];
    float* out = (float*)d_out;

    float *qkv_p = nullptr;
    __nv_bfloat16 *x2_p = nullptr, *o2_p = nullptr, *wq2_p = nullptr, *wp2_p = nullptr;
    cudaGetSymbolAddress((void**)&qkv_p, g_qkv);
    cudaGetSymbolAddress((void**)&x2_p, g_x2);
    cudaGetSymbolAddress((void**)&o2_p, g_o2);
    cudaGetSymbolAddress((void**)&wq2_p, g_wq2);
    cudaGetSymbolAddress((void**)&wp2_p, g_wp2);

    cudaFuncSetAttribute(gemm_mma, cudaFuncAttributeMaxDynamicSharedMemorySize, GSMEM);

    // 0) bf16 splits of x and weights
    split_kernel<<<MM, 256>>>(x, x2_p, MM);
    split_kernel<<<C3, 256>>>(qkv_w, wq2_p, C3);
    split_kernel<<<CC, 256>>>(proj_w, wp2_p, CC);
    // 1) qkv = x @ qkv_w^T  (HMMA, bf16-split, fp32 accumulate)
    gemm_mma<<<dim3(C3 / GBN, MM / GBM), 256, GSMEM>>>(x2_p, wq2_p, nullptr, qkv_p, C3);
    // 2) focusing / activation (in-place on q,k)
    focus_kernel<<<MM, 256>>>(scale, pos_enc);
    // 3) kv = k^T v (+ ksum)
    zero_kv_kernel<<<(BH * DD * DD + 255) / 256, 256>>>();
    kv_kernel<<<dim3(BH, NSPLIT), 64>>>();
    // 4) o = z * (q @ kv), written as split bf16 in merged-head layout
    o_kernel<<<dim3(BH, SEQ / 64), 256>>>();
    // 5) out = o @ proj_w^T + proj_b  (HMMA)
    gemm_mma<<<dim3(CC / GBN, MM / GBM), 256, GSMEM>>>(o2_p, wp2_p, proj_b, out, CC);
}

// round 4
// speedup vs baseline: 2.4203x; 1.0695x over previous
#include <cuda_runtime.h>
#include <cuda_bf16.h>
#include <cstdint>
#include <cstddef>

// Problem constants
#define BB 8
#define SEQ 4096
#define CC 1024
#define HH 16
#define DD 64
#define MM (BB*SEQ)          // 32768
#define C3 (3*CC)            // 3072
#define BH (BB*HH)           // 128
#define EPS 1e-6f
#define K2 2048              // split operand width (hi | lo)

// ---------------- scratch (device globals; no allocation allowed) ----------------
__device__ float g_qkv[(size_t)MM * C3];          // q | k | v  (f32, focus in-place)
__device__ float g_kv[(size_t)BH * DD * DD];
__device__ float g_ksum[BH * DD];
__device__ __nv_bfloat16 g_x2[(size_t)MM * K2];   // x split   [M][hi(1024)|lo(1024)]
__device__ __nv_bfloat16 g_o2[(size_t)MM * K2];   // o split
__device__ __nv_bfloat16 g_wq2[(size_t)C3 * K2];  // qkv_w split
__device__ __nv_bfloat16 g_wp2[(size_t)CC * K2];  // proj_w split

// ================================ helpers ========================================
__device__ __forceinline__ uint32_t smem_u32(const void* p) {
    uint32_t a;
    asm("{ .reg .u64 t; cvta.to.shared.u64 t, %1; cvt.u32.u64 %0, t; }" : "=r"(a) : "l"(p));
    return a;
}
__device__ __forceinline__ void cpa16(uint32_t sa, const void* g) {
    size_t ga = __cvta_generic_to_global(g);
    asm volatile("cp.async.cg.shared.global [%0], [%1], 16;" :: "r"(sa), "l"(ga) : "memory");
}
__device__ __forceinline__ void ldsm4(uint32_t* d, uint32_t addr) {
    asm volatile("ldmatrix.sync.aligned.m8n8.x4.shared.b16 {%0,%1,%2,%3}, [%4];"
        : "=r"(d[0]), "=r"(d[1]), "=r"(d[2]), "=r"(d[3]) : "r"(addr));
}
__device__ __forceinline__ void mma_bf16(float* c, const uint32_t* a, const uint32_t* b) {
    asm volatile("mma.sync.aligned.m16n8k16.row.col.f32.bf16.bf16.f32 "
        "{%0,%1,%2,%3}, {%4,%5,%6,%7}, {%8,%9}, {%0,%1,%2,%3};"
        : "+f"(c[0]), "+f"(c[1]), "+f"(c[2]), "+f"(c[3])
        : "r"(a[0]), "r"(a[1]), "r"(a[2]), "r"(a[3]), "r"(b[0]), "r"(b[1]));
}
#define SW128(o) ((o) ^ (((o) >> 3) & 0x70))

// ============================ HMMA split GEMM ====================================
// C[m,n] = sum_k A[m,k]*B[n,k] (fp32 via bf16 split: Ah*Bh + Al*Bh + Ah*Bl)
// BM=128, BN=128, BK=64; 256 threads; warp tile 64x32 (2x4); 3-stage cp.async.
#define GBM 128
#define GBN 128
#define GBK 64
#define NCH (CC / GBK)          // 16 k-chunks
#define MATB (128 * 128)        // 16384 B per matrix tile (128 rows x 128B, SW128)
#define STG (4 * MATB)          // Ah|Al|Bh|Bl = 65536 B per stage
#define NSTG 3
#define GSMEM (NSTG * STG)      // 196608 B

__device__ __forceinline__ void g2s_chunk(uint32_t sbase,
    const __nv_bfloat16* __restrict__ A2, const __nv_bfloat16* __restrict__ B2,
    int m0, int n0, int k0, int t)
{
#pragma unroll
    for (int i = 0; i < 4; i++) {
        int idx = t + i * 256;            // 1024 16B-chunks per matrix
        int r = idx >> 3, j = idx & 7;
        uint32_t off = r * 128 + j * 16;
        uint32_t sw = SW128(off);
        const __nv_bfloat16* ga = A2 + (size_t)(m0 + r) * K2 + k0 + j * 8;
        cpa16(sbase + 0 * MATB + sw, ga);
        cpa16(sbase + 1 * MATB + sw, ga + CC);
        const __nv_bfloat16* gb = B2 + (size_t)(n0 + r) * K2 + k0 + j * 8;
        cpa16(sbase + 2 * MATB + sw, gb);
        cpa16(sbase + 3 * MATB + sw, gb + CC);
    }
}

__global__ __launch_bounds__(256) void gemm_mma(
    const __nv_bfloat16* __restrict__ A2, const __nv_bfloat16* __restrict__ B2,
    const float* __restrict__ bias, float* __restrict__ C, int Nn)
{
    extern __shared__ char sm[];
    const uint32_t sb = smem_u32(sm);
    const int t = threadIdx.x, lane = t & 31, w = t >> 5;
    const int wm = (w >> 2) * 64, wn = (w & 3) * 32;
    const int m0 = blockIdx.y * GBM, n0 = blockIdx.x * GBN;

    const int lrow = lane & 15;           // ldmatrix source row within 16
    const int lcol = (lane >> 4) << 3;    // ldmatrix k-col select (0 or 8)

    float acc[4][4][4];
#pragma unroll
    for (int i = 0; i < 4; i++)
#pragma unroll
        for (int j = 0; j < 4; j++)
#pragma unroll
            for (int r = 0; r < 4; r++) acc[i][j][r] = 0.f;

    // prologue: chunks 0,1 into stages 0,1
    g2s_chunk(sb, A2, B2, m0, n0, 0, t);
    asm volatile("cp.async.commit_group;" ::: "memory");
    g2s_chunk(sb + STG, A2, B2, m0, n0, GBK, t);
    asm volatile("cp.async.commit_group;" ::: "memory");

    int stage = 0, wstage = 2;
    for (int c = 0; c < NCH; c++) {
        if (c == NCH - 1) asm volatile("cp.async.wait_group 0;" ::: "memory");
        else              asm volatile("cp.async.wait_group 1;" ::: "memory");
        __syncthreads();
        // issue prefetch of chunk c+2 into stage (c+2)%3 (safe: computed at c-1, all warps synced)
        if (c + 2 < NCH) {
            g2s_chunk(sb + wstage * STG, A2, B2, m0, n0, (c + 2) * GBK, t);
            asm volatile("cp.async.commit_group;" ::: "memory");
            wstage = wstage == 2 ? 0 : wstage + 1;
        }
        const uint32_t st = sb + stage * STG;
        stage = stage == 2 ? 0 : stage + 1;

#pragma unroll
        for (int ks = 0; ks < 4; ks++) {
            const int kb = ks * 16;
            uint32_t ah[4][4], al[4][4];
#pragma unroll
            for (int mi = 0; mi < 4; mi++) {
                uint32_t off = (wm + mi * 16 + lrow) * 128 + (kb + lcol) * 2;
                uint32_t sw = SW128(off);
                ldsm4(ah[mi], st + sw);
                ldsm4(al[mi], st + MATB + sw);
            }
            uint32_t bh[4][2], bl[4][2];
#pragma unroll
            for (int bj = 0; bj < 2; bj++) {
                uint32_t r4[4], s4[4];
                uint32_t off = (wn + bj * 16 + lrow) * 128 + (kb + lcol) * 2;
                uint32_t sw = SW128(off);
                ldsm4(r4, st + 2 * MATB + sw);
                ldsm4(s4, st + 3 * MATB + sw);
                bh[2 * bj + 0][0] = r4[0]; bh[2 * bj + 0][1] = r4[2];
                bh[2 * bj + 1][0] = r4[1]; bh[2 * bj + 1][1] = r4[3];
                bl[2 * bj + 0][0] = s4[0]; bl[2 * bj + 0][1] = s4[2];
                bl[2 * bj + 1][0] = s4[1]; bl[2 * bj + 1][1] = s4[3];
            }
            // 3 product passes; consecutive MMAs hit independent accumulators
#pragma unroll
            for (int mi = 0; mi < 4; mi++)
#pragma unroll
                for (int nj = 0; nj < 4; nj++)
                    mma_bf16(acc[mi][nj], ah[mi], bh[nj]);
#pragma unroll
            for (int mi = 0; mi < 4; mi++)
#pragma unroll
                for (int nj = 0; nj < 4; nj++)
                    mma_bf16(acc[mi][nj], al[mi], bh[nj]);
#pragma unroll
            for (int mi = 0; mi < 4; mi++)
#pragma unroll
                for (int nj = 0; nj < 4; nj++)
                    mma_bf16(acc[mi][nj], ah[mi], bl[nj]);
        }
    }

    // epilogue
    const int group = lane >> 2, tig = lane & 3;
#pragma unroll
    for (int mi = 0; mi < 4; mi++)
#pragma unroll
        for (int nj = 0; nj < 4; nj++) {
            int r0 = m0 + wm + mi * 16 + group;
            int cc0 = n0 + wn + nj * 8 + tig * 2;
            float b0 = 0.f, b1 = 0.f;
            if (bias) { b0 = bias[cc0]; b1 = bias[cc0 + 1]; }
            float2 v0 = make_float2(acc[mi][nj][0] + b0, acc[mi][nj][1] + b1);
            float2 v1 = make_float2(acc[mi][nj][2] + b0, acc[mi][nj][3] + b1);
            *(float2*)(C + (size_t)r0 * Nn + cc0)       = v0;
            *(float2*)(C + (size_t)(r0 + 8) * Nn + cc0) = v1;
        }
}

// ============================ split f32 -> (hi|lo) bf16 ==========================
__global__ __launch_bounds__(256) void split_kernel(
    const float* __restrict__ in, __nv_bfloat16* __restrict__ out, int rows)
{
    size_t idx = (size_t)blockIdx.x * 256 + threadIdx.x;
    size_t row = idx >> 8;
    if (row >= (size_t)rows) return;
    int c4 = (int)(idx & 255) << 2;
    float4 v = *(const float4*)(in + row * CC + c4);
    float vv[4] = {v.x, v.y, v.z, v.w};
    __nv_bfloat16 hb[4], lb[4];
#pragma unroll
    for (int j = 0; j < 4; j++) {
        hb[j] = __float2bfloat16(vv[j]);
        lb[j] = __float2bfloat16(vv[j] - __bfloat162float(hb[j]));
    }
    *(uint64_t*)(out + row * K2 + c4)      = *(uint64_t*)hb;
    *(uint64_t*)(out + row * K2 + CC + c4) = *(uint64_t*)lb;
}

// ================================== focus ========================================
__global__ __launch_bounds__(256) void focus_kernel(
    const float* __restrict__ scale, const float* __restrict__ pos_enc)
{
    const int row = blockIdx.x;
    const int n = row & (SEQ - 1);
    float* qp = g_qkv + (size_t)row * C3;
    float* kp = qp + CC;
    const int t = threadIdx.x;
    const int c0 = t * 4;

    float4 q4 = *(float4*)(qp + c0);
    float4 k4 = *(float4*)(kp + c0);
    const float4 pe  = *(const float4*)(pos_enc + (size_t)n * CC + c0);
    const float4 sc4 = *(const float4*)(scale + c0);

    float qv[4] = {q4.x, q4.y, q4.z, q4.w};
    float kv[4] = {k4.x + pe.x, k4.y + pe.y, k4.z + pe.z, k4.w + pe.w};
    float sv[4] = {sc4.x, sc4.y, sc4.z, sc4.w};

    float s2q = 0.f, s6q = 0.f, s2k = 0.f, s6k = 0.f;
#pragma unroll
    for (int j = 0; j < 4; j++) {
        float sc = log1pf(expf(sv[j]));
        float q = (fmaxf(qv[j], 0.f) + EPS) / sc;
        float k = (fmaxf(kv[j], 0.f) + EPS) / sc;
        qv[j] = q; kv[j] = k;
        float q2 = q * q, k2 = k * k;
        s2q += q2; s2k += k2;
        float q3 = q2 * q, k3 = k2 * k;
        s6q += q3 * q3; s6k += k3 * k3;
    }
    __shared__ float red[8][4];
    const int lid = t & 31, wid = t >> 5;
#pragma unroll
    for (int o = 16; o > 0; o >>= 1) {
        s2q += __shfl_xor_sync(0xffffffffu, s2q, o);
        s6q += __shfl_xor_sync(0xffffffffu, s6q, o);
        s2k += __shfl_xor_sync(0xffffffffu, s2k, o);
        s6k += __shfl_xor_sync(0xffffffffu, s6k, o);
    }
    if (lid == 0) { red[wid][0] = s2q; red[wid][1] = s6q; red[wid][2] = s2k; red[wid][3] = s6k; }
    __syncthreads();
    float t2q = 0.f, t6q = 0.f, t2k = 0.f, t6k = 0.f;
#pragma unroll
    for (int wq = 0; wq < 8; wq++) {
        t2q += red[wq][0]; t6q += red[wq][1]; t2k += red[wq][2]; t6k += red[wq][3];
    }
    const float fq = sqrtf(t2q / t6q);
    const float fk = sqrtf(t2k / t6k);

    float4 qo, ko;
    float* qvo = (float*)&qo; float* kvo = (float*)&ko;
#pragma unroll
    for (int j = 0; j < 4; j++) {
        qvo[j] = qv[j] * qv[j] * qv[j] * fq;
        kvo[j] = kv[j] * kv[j] * kv[j] * fk;
    }
    *(float4*)(qp + c0) = qo;
    *(float4*)(kp + c0) = ko;
}

__global__ void zero_kv_kernel()
{
    int i = blockIdx.x * 256 + threadIdx.x;
    if (i < BH * DD * DD) g_kv[i] = 0.f;
    if (i < BH * DD)      g_ksum[i] = 0.f;
}

// ==================================== kv =========================================
#define NSPLIT 8
#define NCHUNK (SEQ / NSPLIT)
__global__ __launch_bounds__(64) void kv_kernel()
{
    const int bh = blockIdx.x;
    const int sp = blockIdx.y;
    const int b = bh >> 4, h = bh & 15;
    const int n0 = sp * NCHUNK;
    __shared__ float ks[32][64];
    __shared__ float vs[32][64];
    const int t = threadIdx.x;
    const int tc = (t >> 3) << 3;
    const int td = (t & 7) << 3;
    unsigned long long acc2[8][4];
#pragma unroll
    for (int i = 0; i < 8; i++)
#pragma unroll
        for (int j = 0; j < 4; j++) acc2[i][j] = 0ULL;
    float ksacc = 0.f;

    for (int nt = 0; nt < NCHUNK; nt += 32) {
#pragma unroll
        for (int l = 0; l < 8; l++) {
            int idx4 = t + l * 64;
            int nn = idx4 >> 4, q4 = (idx4 & 15) << 2;
            size_t base = ((size_t)(b * SEQ + n0 + nt + nn)) * C3 + h * DD + q4;
            *(float4*)&ks[nn][q4] = *(const float4*)&g_qkv[base + CC];
            *(float4*)&vs[nn][q4] = *(const float4*)&g_qkv[base + 2 * CC];
        }
        __syncthreads();
#pragma unroll 4
        for (int nn = 0; nn < 32; nn++) {
            float a[8];
            *(float4*)(a)      = *(float4*)&ks[nn][tc];
            *(float4*)(a + 4)  = *(float4*)&ks[nn][tc + 4];
            unsigned long long b2[4];
            *(ulonglong2*)(b2)     = *(const ulonglong2*)(&vs[nn][td]);
            *(ulonglong2*)(b2 + 2) = *(const ulonglong2*)(&vs[nn][td + 4]);
#pragma unroll
            for (int i = 0; i < 8; i++) {
                unsigned long long a2;
                asm("mov.b64 %0, {%1, %1};" : "=l"(a2) : "f"(a[i]));
#pragma unroll
                for (int j = 0; j < 4; j++)
                    asm("fma.rn.f32x2 %0, %1, %2, %0;" : "+l"(acc2[i][j]) : "l"(a2), "l"(b2[j]));
            }
            ksacc += ks[nn][t];
        }
        __syncthreads();
    }
#pragma unroll
    for (int i = 0; i < 8; i++)
#pragma unroll
        for (int j = 0; j < 4; j++) {
            float lo, hi;
            asm("mov.b64 {%0, %1}, %2;" : "=f"(lo), "=f"(hi) : "l"(acc2[i][j]));
            atomicAdd(&g_kv[((size_t)bh * DD + tc + i) * DD + td + 2 * j], lo);
            atomicAdd(&g_kv[((size_t)bh * DD + tc + i) * DD + td + 2 * j + 1], hi);
        }
    atomicAdd(&g_ksum[bh * DD + t], ksacc);
}

// ============ o kernel: writes split bf16 (hi|lo) directly into g_o2 =============
__global__ __launch_bounds__(256) void o_kernel()
{
    const int bh = blockIdx.x;
    const int ic = blockIdx.y;
    const int b = bh >> 4, h = bh & 15;
    const int i0 = ic * 64;
    __shared__ float qs[64][68];
    __shared__ float kvs[64][64];
    __shared__ float ks_s[64];
    __shared__ float z_s[64];
    const int t = threadIdx.x;

    for (int idx = t; idx < DD * DD; idx += 256)
        kvs[idx >> 6][idx & 63] = g_kv[(size_t)bh * DD * DD + idx];
    if (t < 64) ks_s[t] = g_ksum[bh * DD + t];
    for (int idx = t; idx < 64 * 64; idx += 256) {
        int r = idx >> 6, c = idx & 63;
        qs[c][r] = g_qkv[((size_t)(b * SEQ + i0 + r)) * C3 + h * DD + c];
    }
    __syncthreads();

    if (t < 64) {
        float s = 0.f;
#pragma unroll 8
        for (int c = 0; c < 64; c++) s += qs[c][t] * ks_s[c];
        z_s[t] = 1.0f / (s + EPS);
    }
    __syncthreads();

    const int tm = (t >> 5) << 3;
    const int tn = (t & 31) << 1;
    float acc[8][2] = {};
#pragma unroll 8
    for (int c = 0; c < 64; c++) {
        float a[8];
        *(float4*)(a)     = *(float4*)&qs[c][tm];
        *(float4*)(a + 4) = *(float4*)&qs[c][tm + 4];
        float2 bv = *(float2*)&kvs[c][tn];
#pragma unroll
        for (int i = 0; i < 8; i++) {
            acc[i][0] += a[i] * bv.x;
            acc[i][1] += a[i] * bv.y;
        }
    }
#pragma unroll
    for (int i = 0; i < 8; i++) {
        float z = z_s[tm + i];
        float v0 = acc[i][0] * z, v1 = acc[i][1] * z;
        __nv_bfloat16 hb0 = __float2bfloat16(v0), hb1 = __float2bfloat16(v1);
        __nv_bfloat16 lb0 = __float2bfloat16(v0 - __bfloat162float(hb0));
        __nv_bfloat16 lb1 = __float2bfloat16(v1 - __bfloat162float(hb1));
        size_t off = ((size_t)(b * SEQ + i0 + tm + i)) * K2 + h * DD + tn;
        __nv_bfloat162 hp; hp.x = hb0; hp.y = hb1;
        __nv_bfloat162 lp; lp.x = lb0; lp.y = lb1;
        *(__nv_bfloat162*)(g_o2 + off)      = hp;
        *(__nv_bfloat162*)(g_o2 + off + CC) = lp;
    }
}

// =================================================================================
extern "C" void kernel_launch(void* const* d_in, const int* in_sizes, int n_in,
                              void* d_out, int out_size)
{
    const float* x       = (const float*)d_in[0];
    const float* scale   = (const float*)d_in[1];
    const float* pos_enc = (const float*)d_in[2];
    const float* qkv_w   = (const float*)d_in[3];
    const float* proj_w  = (const float*)d_in[4];
    const float* proj_b  = (const float*)d_in[5];
    float* out = (float*)d_out;

    float *qkv_p = nullptr;
    __nv_bfloat16 *x2_p = nullptr, *o2_p = nullptr, *wq2_p = nullptr, *wp2_p = nullptr;
    cudaGetSymbolAddress((void**)&qkv_p, g_qkv);
    cudaGetSymbolAddress((void**)&x2_p, g_x2);
    cudaGetSymbolAddress((void**)&o2_p, g_o2);
    cudaGetSymbolAddress((void**)&wq2_p, g_wq2);
    cudaGetSymbolAddress((void**)&wp2_p, g_wp2);

    cudaFuncSetAttribute(gemm_mma, cudaFuncAttributeMaxDynamicSharedMemorySize, GSMEM);

    // 0) bf16 splits of x and weights
    split_kernel<<<MM, 256>>>(x, x2_p, MM);
    split_kernel<<<C3, 256>>>(qkv_w, wq2_p, C3);
    split_kernel<<<CC, 256>>>(proj_w, wp2_p, CC);
    // 1) qkv = x @ qkv_w^T  (HMMA, bf16-split, fp32 accumulate)
    gemm_mma<<<dim3(C3 / GBN, MM / GBM), 256, GSMEM>>>(x2_p, wq2_p, nullptr, qkv_p, C3);
    // 2) focusing / activation (in-place on q,k)
    focus_kernel<<<MM, 256>>>(scale, pos_enc);
    // 3) kv = k^T v (+ ksum)
    zero_kv_kernel<<<(BH * DD * DD + 255) / 256, 256>>>();
    kv_kernel<<<dim3(BH, NSPLIT), 64>>>();
    // 4) o = z * (q @ kv), written as split bf16 in merged-head layout
    o_kernel<<<dim3(BH, SEQ / 64), 256>>>();
    // 5) out = o @ proj_w^T + proj_b  (HMMA)
    gemm_mma<<<dim3(CC / GBN, MM / GBM), 256, GSMEM>>>(o2_p, wp2_p, proj_b, out, CC);
}